// round 13
// baseline (speedup 1.0000x reference)
#include <cuda_runtime.h>
#include <cuda_fp16.h>
#include <mma.h>
#include <cstdint>

using namespace nvcuda;

#define HWD   224
#define NPIX  (HWD*HWD)        // 50176
#define BB    2
#define C1    64
#define EE    768
#define MM    196
#define KK    (BB*MM)          // 392
#define PADW  228
#define BNEPS 1e-5f

// ---- static device scratch (no allocation allowed) ----
__device__ __half g_xh[(size_t)BB*PADW*PADW*C1];   // conv1 out (fp16, padded NHWC)
__device__ __half g_whh[9*EE*C1];                  // conv2 w hi: [t][cout][cin], BN-folded
__device__ __half g_whl[9*EE*C1];                  // conv2 w lo (fp16 residual)
__device__ float g_feats[77070336];                // conv2 out NHWC [B][HW][E]
__device__ float g_fconst[EE];
__device__ int   g_cnt[KK];
__device__ float g_sim[KK];
__device__ float g_wk[KK];
__device__ int   g_off[KK+1];
__device__ int   g_cur[KK];
__device__ int   g_plist[BB*NPIX];
__device__ float g_concat[KK*2*EE];

// ------------------------------------------------------------------
__global__ void k_zero() {
    float4* ph = (float4*)g_xh;    // 8 halfs per float4
    const int n4 = ((size_t)BB*PADW*PADW*C1)/8;
    for (int i = blockIdx.x*blockDim.x + threadIdx.x; i < n4; i += gridDim.x*blockDim.x)
        ph[i] = make_float4(0.f,0.f,0.f,0.f);
    if (blockIdx.x == 0) {
        for (int i = threadIdx.x; i < KK; i += blockDim.x) {
            g_cnt[i] = 0; g_sim[i] = 0.f; g_cur[i] = 0;
        }
    }
}

// ------------------------------------------------------------------
__global__ void k_prep_fconst(const float* cb, const float* bg, const float* bb_,
                              const float* bm, const float* bv) {
    int c = threadIdx.x;
    if (c < EE) {
        float inv = bg[c] * rsqrtf(bv[c] + BNEPS);
        g_fconst[c] = cb[c]*inv + bb_[c] - bm[c]*inv;
    }
}

// conv2 weights -> [t][cout][cin] fp16 hi/lo, BN-folded
__global__ void k_prep_wb(const float* w, const float* bg, const float* bv) {
    int i = blockIdx.x*blockDim.x + threadIdx.x;
    const int n = 9*EE*C1;
    if (i < n) {
        int cin  = i & 63;
        int r    = i >> 6;
        int cout = r % EE;
        int t    = r / EE;
        float inv = __ldg(&bg[cout]) * rsqrtf(__ldg(&bv[cout]) + BNEPS);
        float v = __ldg(&w[cout*(C1*9) + cin*9 + t]) * inv;
        __half h = __float2half_rn(v);
        __half l = __float2half_rn(v - __half2float(h));
        g_whh[i] = h; g_whl[i] = l;
    }
}

// ------------------------------------------------------------------
// conv1 3->64, 3x3 pad1 + BN + ReLU, emit fp16 into padded buffer
__global__ void k_conv1(const float* img, const float* w, const float* bias,
                        const float* bg, const float* bb_, const float* bm, const float* bv) {
    int gid = blockIdx.x*blockDim.x + threadIdx.x;
    int cg  = gid & 7;
    int pix = gid >> 3;
    if (pix >= BB*NPIX) return;
    int b = pix / NPIX, p = pix % NPIX;
    int y = p / HWD, x = p % HWD;

    float in[27];
    #pragma unroll
    for (int ci = 0; ci < 3; ci++)
        #pragma unroll
        for (int ky = 0; ky < 3; ky++)
            #pragma unroll
            for (int kx = 0; kx < 3; kx++) {
                int yy = y + ky - 1, xx = x + kx - 1;
                float v = 0.f;
                if (yy >= 0 && yy < HWD && xx >= 0 && xx < HWD)
                    v = __ldg(&img[((b*3 + ci)*HWD + yy)*HWD + xx]);
                in[ci*9 + ky*3 + kx] = v;
            }
    int c0 = cg*8;
    __half hh[8];
    #pragma unroll
    for (int j = 0; j < 8; j++) {
        int c = c0 + j;
        float acc = 0.f;
        #pragma unroll
        for (int q = 0; q < 27; q++) acc += in[q] * __ldg(&w[c*27 + q]);
        float inv = __ldg(&bg[c]) * rsqrtf(__ldg(&bv[c]) + BNEPS);
        float v = (acc + __ldg(&bias[c]))*inv + __ldg(&bb_[c]) - __ldg(&bm[c])*inv;
        hh[j] = __float2half_rn(fmaxf(v, 0.f));
    }
    size_t base = (((size_t)b*PADW + y + 2)*PADW + x + 2)*C1 + c0;
    *(uint4*)&g_xh[base] = *(uint4*)hh;
}

// ------------------------------------------------------------------
__global__ void k_edge(const float* img, const int* seg, const float* ew,
                       float* out, int goff, int soff) {
    __shared__ int   scnt[MM];
    __shared__ float ssim[MM];
    int tid = threadIdx.x;
    if (tid < MM) { scnt[tid] = 0; ssim[tid] = 0.f; }
    __syncthreads();

    int gid = blockIdx.x*256 + tid;
    int b = gid / NPIX, p = gid % NPIX;
    int y = p / HWD, x = p % HWD;

    float e0 = 0.f, e1 = 0.f;
    #pragma unroll
    for (int ky = 0; ky < 3; ky++)
        #pragma unroll
        for (int kx = 0; kx < 3; kx++) {
            int yy = y + ky - 1, xx = x + kx - 1;
            float gr = 0.f;
            if (yy >= 0 && yy < HWD && xx >= 0 && xx < HWD) {
                int base = (b*3*HWD + yy)*HWD + xx;
                gr = (__ldg(&img[base]) + __ldg(&img[base + NPIX]) + __ldg(&img[base + 2*NPIX])) * (1.f/3.f);
            }
            e0 += gr * __ldg(&ew[ky*3 + kx]);
            e1 += gr * __ldg(&ew[9 + ky*3 + kx]);
        }
    float grad = sqrtf(e0*e0 + e1*e1 + 1e-8f);
    float sim  = fminf(fmaxf(1.f - grad, 0.f), 1.f);
    int s = seg[gid];
    if (goff >= 0) out[goff + gid] = grad;
    if (soff >= 0) out[soff + gid] = (float)s;
    atomicAdd(&scnt[s], 1);
    atomicAdd(&ssim[s], sim);
    __syncthreads();
    if (tid < MM) {
        if (scnt[tid]) atomicAdd(&g_cnt[b*MM + tid], scnt[tid]);
        if (ssim[tid] != 0.f) atomicAdd(&g_sim[b*MM + tid], ssim[tid]);
    }
}

// ------------------------------------------------------------------
__global__ void k_scan() {
    __shared__ int s[512];
    int tid = threadIdx.x;
    int v = (tid < KK) ? g_cnt[tid] : 0;
    s[tid] = v;
    __syncthreads();
    for (int d = 1; d < 512; d <<= 1) {
        int t = (tid >= d) ? s[tid - d] : 0;
        __syncthreads();
        s[tid] += t;
        __syncthreads();
    }
    if (tid < KK) {
        g_off[tid] = s[tid] - v;
        g_wk[tid]  = g_sim[tid] / fmaxf((float)v, 1.f);
    }
    if (tid == 0) g_off[KK] = s[511];
}

__global__ void k_scatter(const int* seg) {
    int gid = blockIdx.x*256 + threadIdx.x;
    int b = gid / NPIX, p = gid % NPIX;
    int k = b*MM + seg[gid];
    int pos = atomicAdd(&g_cur[k], 1);
    g_plist[g_off[k] + pos] = p;
}

// ------------------------------------------------------------------
// conv2 via WMMA fp16 2-term: block = 128 px x 128 cout, 8 warps,
// warp = 32 px x 64 cout (2 m-tiles x 4 n-tiles).
// out = xh*whh + xh*whl (w fully compensated; x fp16 error independent per px)
#define LDA 72
#define OFF_A  0
#define OFF_BH (128*LDA)             // elems
#define OFF_BL (2*128*LDA)
#define SMEM_W 65536                 // tiles need 55296; fp32 epilogue needs 65536

__global__ void __launch_bounds__(256) k_conv2_wmma() {
    extern __shared__ __half sm[];
    int tid = threadIdx.x, wid = tid >> 5;
    int p0 = blockIdx.x * 128;
    int c0 = blockIdx.y * 128;
    int b  = blockIdx.z;

    int wm = wid & 3;            // m group: pixels wm*32 .. wm*32+31 (2 tiles)
    int wn = wid >> 2;           // n group: couts wn*64 .. wn*64+63 (4 tiles)

    wmma::fragment<wmma::accumulator, 16, 16, 16, float> acc[2][4];
    #pragma unroll
    for (int i = 0; i < 2; i++)
        #pragma unroll
        for (int j = 0; j < 4; j++) wmma::fill_fragment(acc[i][j], 0.f);

    #pragma unroll 1
    for (int t = 0; t < 9; t++) {
        int ky = t / 3, kx = t - ky*3;
        // ---- stage A: 128 px x 64 cin (1024 uint4) ----
        #pragma unroll
        for (int q = 0; q < 4; q++) {
            int u = q*256 + tid;              // 0..1023
            int px = u >> 3, c8 = u & 7;
            int p = p0 + px;
            int y = p / HWD, x = p - y*HWD;
            const __half* src = g_xh + (((size_t)b*PADW + y + 2*ky)*PADW + (x + 2*kx))*C1;
            uint4 val = *((const uint4*)src + c8);
            *(uint4*)&sm[OFF_A + px*LDA + c8*8] = val;
        }
        // ---- stage B: 128 cout x 64 cin, hi+lo (2048 uint4) ----
        #pragma unroll
        for (int q = 0; q < 8; q++) {
            int u = q*256 + tid;              // 0..2047
            int term = u >> 10;
            int v    = u & 1023;
            int co   = v >> 3, c8 = v & 7;    // co 0..127
            const __half* src = (term ? g_whl : g_whh) + ((size_t)t*EE + c0 + co)*C1;
            uint4 val = *((const uint4*)src + c8);
            *(uint4*)&sm[(term ? OFF_BL : OFF_BH) + co*LDA + c8*8] = val;
        }
        __syncthreads();

        #pragma unroll
        for (int kc = 0; kc < 4; kc++) {
            wmma::fragment<wmma::matrix_a, 16, 16, 16, __half, wmma::row_major> ah[2];
            #pragma unroll
            for (int i = 0; i < 2; i++)
                wmma::load_matrix_sync(ah[i], &sm[OFF_A + (wm*32 + i*16)*LDA + kc*16], LDA);
            #pragma unroll
            for (int j = 0; j < 4; j++) {
                int nrow = wn*64 + j*16;
                wmma::fragment<wmma::matrix_b, 16, 16, 16, __half, wmma::col_major> bh, bl;
                wmma::load_matrix_sync(bh, &sm[OFF_BH + nrow*LDA + kc*16], LDA);
                wmma::load_matrix_sync(bl, &sm[OFF_BL + nrow*LDA + kc*16], LDA);
                #pragma unroll
                for (int i = 0; i < 2; i++) {
                    wmma::mma_sync(acc[i][j], ah[i], bh, acc[i][j]);
                    wmma::mma_sync(acc[i][j], ah[i], bl, acc[i][j]);
                }
            }
        }
        __syncthreads();
    }

    // ---- epilogue: frags -> smem (fp32) -> bias+ReLU -> gmem ----
    float* cs = (float*)sm;      // 128 x 128 floats = 64KB
    #pragma unroll
    for (int i = 0; i < 2; i++)
        #pragma unroll
        for (int j = 0; j < 4; j++)
            wmma::store_matrix_sync(cs + (wm*32 + i*16)*128 + wn*64 + j*16, acc[i][j],
                                    128, wmma::mem_row_major);
    __syncthreads();

    #pragma unroll
    for (int q = 0; q < 16; q++) {
        int u = q*256 + tid;             // float4 index, 0..4095
        int row = u >> 5, col4 = u & 31;
        float4 v = ((const float4*)cs)[u];
        int cb = c0 + col4*4;
        v.x = fmaxf(v.x + __ldg(&g_fconst[cb+0]), 0.f);
        v.y = fmaxf(v.y + __ldg(&g_fconst[cb+1]), 0.f);
        v.z = fmaxf(v.z + __ldg(&g_fconst[cb+2]), 0.f);
        v.w = fmaxf(v.w + __ldg(&g_fconst[cb+3]), 0.f);
        *(float4*)&g_feats[((size_t)b*NPIX + p0 + row)*EE + cb] = v;
    }
}

// ------------------------------------------------------------------
// per-(b,seg) mean/max pooling over pixel list; each thread owns 3 channels
__global__ void k_pool() {
    __shared__ int sp[256];
    int k = blockIdx.x;
    int b = k / MM;
    int tid = threadIdx.x;
    int cnt = g_cnt[k];
    int off = g_off[k];
    const float* fb = g_feats + (size_t)b*NPIX*EE;

    float s0=0.f, s1=0.f, s2=0.f, m0=0.f, m1=0.f, m2=0.f;
    for (int base = 0; base < cnt; base += 256) {
        int nchunk = min(256, cnt - base);
        __syncthreads();
        if (tid < nchunk) sp[tid] = g_plist[off + base + tid];
        __syncthreads();
        int i = 0;
        for (; i + 1 < nchunk; i += 2) {
            const float* f0 = fb + (size_t)sp[i]*EE + tid;
            const float* f1 = fb + (size_t)sp[i+1]*EE + tid;
            float a0 = f0[0], b0 = f0[256], c0v = f0[512];
            float a1 = f1[0], b1 = f1[256], c1v = f1[512];
            s0 += a0 + a1; s1 += b0 + b1; s2 += c0v + c1v;
            m0 = fmaxf(m0, fmaxf(a0, a1));
            m1 = fmaxf(m1, fmaxf(b0, b1));
            m2 = fmaxf(m2, fmaxf(c0v, c1v));
        }
        if (i < nchunk) {
            const float* f0 = fb + (size_t)sp[i]*EE + tid;
            float a0 = f0[0], b0 = f0[256], c0v = f0[512];
            s0 += a0; s1 += b0; s2 += c0v;
            m0 = fmaxf(m0, a0); m1 = fmaxf(m1, b0); m2 = fmaxf(m2, c0v);
        }
    }
    float n = fmaxf((float)cnt, 1.f);
    float* dst = g_concat + (size_t)k*1536;
    dst[tid]        = s0/n;  dst[256 + tid]  = s1/n;  dst[512 + tid]  = s2/n;
    dst[768 + tid]  = m0;    dst[1024 + tid] = m1;    dst[1280 + tid] = m2;
}

// ------------------------------------------------------------------
// fused = concat @ fusion_w^T + b, *W_k, + positional embedding
__global__ void k_fuse(const float* fw, const float* fbias, const float* pw,
                       const float* pb, const float* cent, float* out) {
    __shared__ float As[16][68];
    __shared__ float Bs[16][68];
    int tid = threadIdx.x;
    int d0 = blockIdx.x * 64;
    int r0 = blockIdx.y * 64;
    int tx = tid % 16, ty2 = tid / 16;

    float acc[4][4];
    #pragma unroll
    for (int i = 0; i < 4; i++)
        #pragma unroll
        for (int j = 0; j < 4; j++) acc[i][j] = 0.f;

    for (int kk = 0; kk < 2*EE; kk += 16) {
        {
            int ar = tid >> 2, ac4 = tid & 3;
            int r = r0 + ar;
            float4 v = make_float4(0.f,0.f,0.f,0.f);
            if (r < KK)
                v = ((const float4*)(g_concat + (size_t)r*1536 + kk))[ac4];
            As[ac4*4+0][ar] = v.x; As[ac4*4+1][ar] = v.y;
            As[ac4*4+2][ar] = v.z; As[ac4*4+3][ar] = v.w;
        }
        {
            int dd = tid >> 2, cc4 = tid & 3;
            float4 v = ((const float4*)(fw + (size_t)(d0 + dd)*1536 + kk))[cc4];
            Bs[cc4*4+0][dd] = v.x; Bs[cc4*4+1][dd] = v.y;
            Bs[cc4*4+2][dd] = v.z; Bs[cc4*4+3][dd] = v.w;
        }
        __syncthreads();
        #pragma unroll
        for (int q = 0; q < 16; q++) {
            float4 a = *(const float4*)&As[q][ty2*4];
            float4 bv = *(const float4*)&Bs[q][tx*4];
            const float* ap = (const float*)&a;
            const float* bp = (const float*)&bv;
            #pragma unroll
            for (int i = 0; i < 4; i++)
                #pragma unroll
                for (int j = 0; j < 4; j++)
                    acc[i][j] += ap[i] * bp[j];
        }
        __syncthreads();
    }

    #pragma unroll
    for (int i = 0; i < 4; i++) {
        int r = r0 + ty2*4 + i;
        if (r >= KK) continue;
        float wk = g_wk[r];
        float cx = __ldg(&cent[r*2 + 0]) * (1.f/224.f);
        float cy = __ldg(&cent[r*2 + 1]) * (1.f/224.f);
        #pragma unroll
        for (int j = 0; j < 4; j++) {
            int d = d0 + tx*4 + j;
            float v = (acc[i][j] + __ldg(&fbias[d])) * wk;
            v += cx*__ldg(&pw[d*2 + 0]) + cy*__ldg(&pw[d*2 + 1]) + __ldg(&pb[d]);
            out[(size_t)r*EE + d] = v;
        }
    }
}

// ------------------------------------------------------------------
extern "C" void kernel_launch(void* const* d_in, const int* in_sizes, int n_in,
                              void* d_out, int out_size) {
    const float* img   = (const float*)d_in[0];
    const int*   seg   = (const int*)d_in[1];
    const float* cent  = (const float*)d_in[2];
    const float* c1w   = (const float*)d_in[3];
    const float* c1b   = (const float*)d_in[4];
    const float* bn1g  = (const float*)d_in[5];
    const float* bn1b  = (const float*)d_in[6];
    const float* bn1m  = (const float*)d_in[7];
    const float* bn1v  = (const float*)d_in[8];
    const float* c2w   = (const float*)d_in[9];
    const float* c2b   = (const float*)d_in[10];
    const float* bn2g  = (const float*)d_in[11];
    const float* bn2b  = (const float*)d_in[12];
    const float* bn2m  = (const float*)d_in[13];
    const float* bn2v  = (const float*)d_in[14];
    const float* edgew = (const float*)d_in[15];
    const float* posw  = (const float*)d_in[16];
    const float* posb  = (const float*)d_in[17];
    const float* fusw  = (const float*)d_in[18];
    const float* fusb  = (const float*)d_in[19];
    float* out = (float*)d_out;
    (void)n_in; (void)in_sizes;

    const int FINAL_N = BB*MM*EE;
    int goff = (out_size >= FINAL_N + BB*NPIX)   ? FINAL_N : -1;
    int soff = (out_size >= FINAL_N + 2*BB*NPIX) ? FINAL_N + BB*NPIX : -1;

    cudaFuncSetAttribute(k_conv2_wmma, cudaFuncAttributeMaxDynamicSharedMemorySize, SMEM_W);

    k_zero<<<1024, 256>>>();
    k_prep_fconst<<<1, EE>>>(c2b, bn2g, bn2b, bn2m, bn2v);
    k_prep_wb<<<(9*EE*C1 + 255)/256, 256>>>(c2w, bn2g, bn2v);
    k_conv1<<<(BB*NPIX*8)/256, 256>>>(img, c1w, c1b, bn1g, bn1b, bn1m, bn1v);
    k_edge<<<BB*NPIX/256, 256>>>(img, seg, edgew, out, goff, soff);
    k_scan<<<1, 512>>>();
    k_scatter<<<BB*NPIX/256, 256>>>(seg);
    k_conv2_wmma<<<dim3(NPIX/128, EE/128, BB), 256, SMEM_W>>>();
    k_pool<<<KK, 256>>>();
    k_fuse<<<dim3(EE/64, (KK + 63)/64), 256>>>(fusw, fusb, posw, posb, cent, out);
}

// round 15
// speedup vs baseline: 1.0444x; 1.0444x over previous
#include <cuda_runtime.h>
#include <cuda_fp16.h>
#include <mma.h>
#include <cstdint>

using namespace nvcuda;

#define HWD   224
#define NPIX  (HWD*HWD)        // 50176
#define BB    2
#define C1    64
#define EE    768
#define MM    196
#define KK    (BB*MM)          // 392
#define PADW  228
#define BNEPS 1e-5f

// ---- static device scratch (no allocation allowed) ----
__device__ __half g_xh[(size_t)BB*PADW*PADW*C1];   // conv1 out (fp16, padded NHWC)
__device__ __half g_whh[9*EE*C1];                  // conv2 w hi: [t][cout][cin], BN-folded
__device__ __half g_whl[9*EE*C1];                  // conv2 w lo (fp16 residual)
__device__ float g_feats[77070336];                // conv2 out NHWC [B][HW][E]
__device__ float g_fconst[EE];
__device__ int   g_cnt[KK];
__device__ float g_sim[KK];
__device__ float g_wk[KK];
__device__ int   g_off[KK+1];
__device__ int   g_cur[KK];
__device__ int   g_plist[BB*NPIX];
__device__ float g_concat[KK*2*EE];

// ------------------------------------------------------------------
__global__ void k_zero() {
    float4* ph = (float4*)g_xh;    // 8 halfs per float4
    const int n4 = ((size_t)BB*PADW*PADW*C1)/8;
    for (int i = blockIdx.x*blockDim.x + threadIdx.x; i < n4; i += gridDim.x*blockDim.x)
        ph[i] = make_float4(0.f,0.f,0.f,0.f);
    if (blockIdx.x == 0) {
        for (int i = threadIdx.x; i < KK; i += blockDim.x) {
            g_cnt[i] = 0; g_sim[i] = 0.f; g_cur[i] = 0;
        }
    }
}

// ------------------------------------------------------------------
__global__ void k_prep_fconst(const float* cb, const float* bg, const float* bb_,
                              const float* bm, const float* bv) {
    int c = threadIdx.x;
    if (c < EE) {
        float inv = bg[c] * rsqrtf(bv[c] + BNEPS);
        g_fconst[c] = cb[c]*inv + bb_[c] - bm[c]*inv;
    }
}

// conv2 weights -> [t][cout][cin] fp16 hi/lo, BN-folded
__global__ void k_prep_wb(const float* w, const float* bg, const float* bv) {
    int i = blockIdx.x*blockDim.x + threadIdx.x;
    const int n = 9*EE*C1;
    if (i < n) {
        int cin  = i & 63;
        int r    = i >> 6;
        int cout = r % EE;
        int t    = r / EE;
        float inv = __ldg(&bg[cout]) * rsqrtf(__ldg(&bv[cout]) + BNEPS);
        float v = __ldg(&w[cout*(C1*9) + cin*9 + t]) * inv;
        __half h = __float2half_rn(v);
        __half l = __float2half_rn(v - __half2float(h));
        g_whh[i] = h; g_whl[i] = l;
    }
}

// ------------------------------------------------------------------
// conv1 3->64, 3x3 pad1 + BN + ReLU, fp16 out. 4 threads/pixel x 16 couts
// (halves the redundant 27-tap input loads vs 8 threads/pixel).
__global__ void k_conv1(const float* img, const float* w, const float* bias,
                        const float* bg, const float* bb_, const float* bm, const float* bv) {
    int gid = blockIdx.x*blockDim.x + threadIdx.x;   // B*NPIX*4 threads
    int cg  = gid & 3;
    int pix = gid >> 2;
    if (pix >= BB*NPIX) return;
    int b = pix / NPIX, p = pix % NPIX;
    int y = p / HWD, x = p % HWD;

    float in[27];
    #pragma unroll
    for (int ci = 0; ci < 3; ci++)
        #pragma unroll
        for (int ky = 0; ky < 3; ky++)
            #pragma unroll
            for (int kx = 0; kx < 3; kx++) {
                int yy = y + ky - 1, xx = x + kx - 1;
                float v = 0.f;
                if (yy >= 0 && yy < HWD && xx >= 0 && xx < HWD)
                    v = __ldg(&img[((b*3 + ci)*HWD + yy)*HWD + xx]);
                in[ci*9 + ky*3 + kx] = v;
            }
    int c0 = cg*16;
    __half hh[16];
    #pragma unroll
    for (int j = 0; j < 16; j++) {
        int c = c0 + j;
        float acc = 0.f;
        #pragma unroll
        for (int q = 0; q < 27; q++) acc += in[q] * __ldg(&w[c*27 + q]);
        float inv = __ldg(&bg[c]) * rsqrtf(__ldg(&bv[c]) + BNEPS);
        float v = (acc + __ldg(&bias[c]))*inv + __ldg(&bb_[c]) - __ldg(&bm[c])*inv;
        hh[j] = __float2half_rn(fmaxf(v, 0.f));
    }
    size_t base = (((size_t)b*PADW + y + 2)*PADW + x + 2)*C1 + c0;
    *(uint4*)&g_xh[base]     = *(uint4*)hh;
    *(uint4*)&g_xh[base + 8] = *(uint4*)&hh[8];
}

// ------------------------------------------------------------------
__global__ void k_edge(const float* img, const int* seg, const float* ew,
                       float* out, int goff, int soff) {
    __shared__ int   scnt[MM];
    __shared__ float ssim[MM];
    int tid = threadIdx.x;
    if (tid < MM) { scnt[tid] = 0; ssim[tid] = 0.f; }
    __syncthreads();

    int gid = blockIdx.x*256 + tid;
    int b = gid / NPIX, p = gid % NPIX;
    int y = p / HWD, x = p % HWD;

    float e0 = 0.f, e1 = 0.f;
    #pragma unroll
    for (int ky = 0; ky < 3; ky++)
        #pragma unroll
        for (int kx = 0; kx < 3; kx++) {
            int yy = y + ky - 1, xx = x + kx - 1;
            float gr = 0.f;
            if (yy >= 0 && yy < HWD && xx >= 0 && xx < HWD) {
                int base = (b*3*HWD + yy)*HWD + xx;
                gr = (__ldg(&img[base]) + __ldg(&img[base + NPIX]) + __ldg(&img[base + 2*NPIX])) * (1.f/3.f);
            }
            e0 += gr * __ldg(&ew[ky*3 + kx]);
            e1 += gr * __ldg(&ew[9 + ky*3 + kx]);
        }
    float grad = sqrtf(e0*e0 + e1*e1 + 1e-8f);
    float sim  = fminf(fmaxf(1.f - grad, 0.f), 1.f);
    int s = seg[gid];
    if (goff >= 0) out[goff + gid] = grad;
    if (soff >= 0) out[soff + gid] = (float)s;
    atomicAdd(&scnt[s], 1);
    atomicAdd(&ssim[s], sim);
    __syncthreads();
    if (tid < MM) {
        if (scnt[tid]) atomicAdd(&g_cnt[b*MM + tid], scnt[tid]);
        if (ssim[tid] != 0.f) atomicAdd(&g_sim[b*MM + tid], ssim[tid]);
    }
}

// ------------------------------------------------------------------
__global__ void k_scan() {
    __shared__ int s[512];
    int tid = threadIdx.x;
    int v = (tid < KK) ? g_cnt[tid] : 0;
    s[tid] = v;
    __syncthreads();
    for (int d = 1; d < 512; d <<= 1) {
        int t = (tid >= d) ? s[tid - d] : 0;
        __syncthreads();
        s[tid] += t;
        __syncthreads();
    }
    if (tid < KK) {
        g_off[tid] = s[tid] - v;
        g_wk[tid]  = g_sim[tid] / fmaxf((float)v, 1.f);
    }
    if (tid == 0) g_off[KK] = s[511];
}

__global__ void k_scatter(const int* seg) {
    int gid = blockIdx.x*256 + threadIdx.x;
    int b = gid / NPIX, p = gid % NPIX;
    int k = b*MM + seg[gid];
    int pos = atomicAdd(&g_cur[k], 1);
    g_plist[g_off[k] + pos] = p;
}

// ------------------------------------------------------------------
// conv2 via WMMA fp16 2-term + cp.async double-buffered staging.
// block = 128 px x 128 cout, 8 warps, warp = 32 px x 64 cout.
#define LDA 72
#define STAGE_H (3*128*LDA)          // halfs per stage buffer (A + BH + BL)
#define OFF_BH (128*LDA)
#define OFF_BL (2*128*LDA)
#define SMEM_W (2*STAGE_H*2)         // 110592 bytes

__device__ __forceinline__ void cp16(uint32_t dst, const void* src) {
    asm volatile("cp.async.cg.shared.global [%0], [%1], 16;" :: "r"(dst), "l"(src) : "memory");
}

__global__ void __launch_bounds__(256) k_conv2_wmma() {
    extern __shared__ __half sm[];
    uint32_t smb = (uint32_t)__cvta_generic_to_shared(sm);
    int tid = threadIdx.x, wid = tid >> 5;
    int p0 = blockIdx.x * 128;
    int c0 = blockIdx.y * 128;
    int b  = blockIdx.z;

    int wm = wid & 3;            // m group: pixels wm*32 .. +31 (2 tiles)
    int wn = wid >> 2;           // n group: couts wn*64 .. +63 (4 tiles)

    wmma::fragment<wmma::accumulator, 16, 16, 16, float> acc[2][4];
    #pragma unroll
    for (int i = 0; i < 2; i++)
        #pragma unroll
        for (int j = 0; j < 4; j++) wmma::fill_fragment(acc[i][j], 0.f);

    // ---- async stage of tap t into buffer buf ----
    auto stage = [&](int t, int buf) {
        int ky = t / 3, kx = t - ky*3;
        uint32_t base = smb + (uint32_t)buf*STAGE_H*2;
        // A: 128 px x 64 cin (1024 x 16B)
        #pragma unroll
        for (int q = 0; q < 4; q++) {
            int u = q*256 + tid;
            int px = u >> 3, c8 = u & 7;
            int p = p0 + px;
            int y = p / HWD, x = p - y*HWD;
            const __half* src = g_xh + (((size_t)b*PADW + y + 2*ky)*PADW + (x + 2*kx))*C1 + c8*8;
            cp16(base + (uint32_t)(px*LDA + c8*8)*2, src);
        }
        // B: 128 cout x 64 cin, hi+lo (2048 x 16B)
        #pragma unroll
        for (int q = 0; q < 8; q++) {
            int u = q*256 + tid;
            int term = u >> 10;
            int v    = u & 1023;
            int co   = v >> 3, c8 = v & 7;
            const __half* src = (term ? g_whl : g_whh) + ((size_t)t*EE + c0 + co)*C1 + c8*8;
            cp16(base + (uint32_t)((term ? OFF_BL : OFF_BH) + co*LDA + c8*8)*2, src);
        }
        asm volatile("cp.async.commit_group;" ::: "memory");
    };

    stage(0, 0);

    #pragma unroll 1
    for (int t = 0; t < 9; t++) {
        asm volatile("cp.async.wait_group 0;" ::: "memory");
        __syncthreads();                       // tiles of tap t visible; prior compute done
        if (t < 8) stage(t + 1, (t + 1) & 1);  // overlap with compute below

        const __half* buf = sm + (t & 1)*STAGE_H;
        #pragma unroll
        for (int kc = 0; kc < 4; kc++) {
            wmma::fragment<wmma::matrix_a, 16, 16, 16, __half, wmma::row_major> ah[2];
            #pragma unroll
            for (int i = 0; i < 2; i++)
                wmma::load_matrix_sync(ah[i], &buf[(wm*32 + i*16)*LDA + kc*16], LDA);
            #pragma unroll
            for (int j = 0; j < 4; j++) {
                int nrow = wn*64 + j*16;
                wmma::fragment<wmma::matrix_b, 16, 16, 16, __half, wmma::col_major> bh, bl;
                wmma::load_matrix_sync(bh, &buf[OFF_BH + nrow*LDA + kc*16], LDA);
                wmma::load_matrix_sync(bl, &buf[OFF_BL + nrow*LDA + kc*16], LDA);
                #pragma unroll
                for (int i = 0; i < 2; i++) {
                    wmma::mma_sync(acc[i][j], ah[i], bh, acc[i][j]);
                    wmma::mma_sync(acc[i][j], ah[i], bl, acc[i][j]);
                }
            }
        }
    }

    // ---- epilogue: frags -> smem (fp32, reuse tile mem) -> bias+ReLU -> gmem ----
    __syncthreads();
    float* cs = (float*)sm;      // 128 x 128 floats = 64KB <= 108KB
    #pragma unroll
    for (int i = 0; i < 2; i++)
        #pragma unroll
        for (int j = 0; j < 4; j++)
            wmma::store_matrix_sync(cs + (wm*32 + i*16)*128 + wn*64 + j*16, acc[i][j],
                                    128, wmma::mem_row_major);
    __syncthreads();

    #pragma unroll
    for (int q = 0; q < 16; q++) {
        int u = q*256 + tid;             // float4 index, 0..4095
        int row = u >> 5, col4 = u & 31;
        float4 v = ((const float4*)cs)[u];
        int cb = c0 + col4*4;
        v.x = fmaxf(v.x + __ldg(&g_fconst[cb+0]), 0.f);
        v.y = fmaxf(v.y + __ldg(&g_fconst[cb+1]), 0.f);
        v.z = fmaxf(v.z + __ldg(&g_fconst[cb+2]), 0.f);
        v.w = fmaxf(v.w + __ldg(&g_fconst[cb+3]), 0.f);
        *(float4*)&g_feats[((size_t)b*NPIX + p0 + row)*EE + cb] = v;
    }
}

// ------------------------------------------------------------------
// per-(b,seg) mean/max pooling over pixel list; each thread owns 3 channels
__global__ void k_pool() {
    __shared__ int sp[256];
    int k = blockIdx.x;
    int b = k / MM;
    int tid = threadIdx.x;
    int cnt = g_cnt[k];
    int off = g_off[k];
    const float* fb = g_feats + (size_t)b*NPIX*EE;

    float s0=0.f, s1=0.f, s2=0.f, m0=0.f, m1=0.f, m2=0.f;
    for (int base = 0; base < cnt; base += 256) {
        int nchunk = min(256, cnt - base);
        __syncthreads();
        if (tid < nchunk) sp[tid] = g_plist[off + base + tid];
        __syncthreads();
        int i = 0;
        for (; i + 1 < nchunk; i += 2) {
            const float* f0 = fb + (size_t)sp[i]*EE + tid;
            const float* f1 = fb + (size_t)sp[i+1]*EE + tid;
            float a0 = f0[0], b0 = f0[256], c0v = f0[512];
            float a1 = f1[0], b1 = f1[256], c1v = f1[512];
            s0 += a0 + a1; s1 += b0 + b1; s2 += c0v + c1v;
            m0 = fmaxf(m0, fmaxf(a0, a1));
            m1 = fmaxf(m1, fmaxf(b0, b1));
            m2 = fmaxf(m2, fmaxf(c0v, c1v));
        }
        if (i < nchunk) {
            const float* f0 = fb + (size_t)sp[i]*EE + tid;
            float a0 = f0[0], b0 = f0[256], c0v = f0[512];
            s0 += a0; s1 += b0; s2 += c0v;
            m0 = fmaxf(m0, a0); m1 = fmaxf(m1, b0); m2 = fmaxf(m2, c0v);
        }
    }
    float n = fmaxf((float)cnt, 1.f);
    float* dst = g_concat + (size_t)k*1536;
    dst[tid]        = s0/n;  dst[256 + tid]  = s1/n;  dst[512 + tid]  = s2/n;
    dst[768 + tid]  = m0;    dst[1024 + tid] = m1;    dst[1280 + tid] = m2;
}

// ------------------------------------------------------------------
// fused = concat @ fusion_w^T + b, *W_k, + positional embedding
__global__ void k_fuse(const float* fw, const float* fbias, const float* pw,
                       const float* pb, const float* cent, float* out) {
    __shared__ float As[16][68];
    __shared__ float Bs[16][68];
    int tid = threadIdx.x;
    int d0 = blockIdx.x * 64;
    int r0 = blockIdx.y * 64;
    int tx = tid % 16, ty2 = tid / 16;

    float acc[4][4];
    #pragma unroll
    for (int i = 0; i < 4; i++)
        #pragma unroll
        for (int j = 0; j < 4; j++) acc[i][j] = 0.f;

    for (int kk = 0; kk < 2*EE; kk += 16) {
        {
            int ar = tid >> 2, ac4 = tid & 3;
            int r = r0 + ar;
            float4 v = make_float4(0.f,0.f,0.f,0.f);
            if (r < KK)
                v = ((const float4*)(g_concat + (size_t)r*1536 + kk))[ac4];
            As[ac4*4+0][ar] = v.x; As[ac4*4+1][ar] = v.y;
            As[ac4*4+2][ar] = v.z; As[ac4*4+3][ar] = v.w;
        }
        {
            int dd = tid >> 2, cc4 = tid & 3;
            float4 v = ((const float4*)(fw + (size_t)(d0 + dd)*1536 + kk))[cc4];
            Bs[cc4*4+0][dd] = v.x; Bs[cc4*4+1][dd] = v.y;
            Bs[cc4*4+2][dd] = v.z; Bs[cc4*4+3][dd] = v.w;
        }
        __syncthreads();
        #pragma unroll
        for (int q = 0; q < 16; q++) {
            float4 a = *(const float4*)&As[q][ty2*4];
            float4 bv = *(const float4*)&Bs[q][tx*4];
            const float* ap = (const float*)&a;
            const float* bp = (const float*)&bv;
            #pragma unroll
            for (int i = 0; i < 4; i++)
                #pragma unroll
                for (int j = 0; j < 4; j++)
                    acc[i][j] += ap[i] * bp[j];
        }
        __syncthreads();
    }

    #pragma unroll
    for (int i = 0; i < 4; i++) {
        int r = r0 + ty2*4 + i;
        if (r >= KK) continue;
        float wk = g_wk[r];
        float cx = __ldg(&cent[r*2 + 0]) * (1.f/224.f);
        float cy = __ldg(&cent[r*2 + 1]) * (1.f/224.f);
        #pragma unroll
        for (int j = 0; j < 4; j++) {
            int d = d0 + tx*4 + j;
            float v = (acc[i][j] + __ldg(&fbias[d])) * wk;
            v += cx*__ldg(&pw[d*2 + 0]) + cy*__ldg(&pw[d*2 + 1]) + __ldg(&pb[d]);
            out[(size_t)r*EE + d] = v;
        }
    }
}

// ------------------------------------------------------------------
extern "C" void kernel_launch(void* const* d_in, const int* in_sizes, int n_in,
                              void* d_out, int out_size) {
    const float* img   = (const float*)d_in[0];
    const int*   seg   = (const int*)d_in[1];
    const float* cent  = (const float*)d_in[2];
    const float* c1w   = (const float*)d_in[3];
    const float* c1b   = (const float*)d_in[4];
    const float* bn1g  = (const float*)d_in[5];
    const float* bn1b  = (const float*)d_in[6];
    const float* bn1m  = (const float*)d_in[7];
    const float* bn1v  = (const float*)d_in[8];
    const float* c2w   = (const float*)d_in[9];
    const float* c2b   = (const float*)d_in[10];
    const float* bn2g  = (const float*)d_in[11];
    const float* bn2b  = (const float*)d_in[12];
    const float* bn2m  = (const float*)d_in[13];
    const float* bn2v  = (const float*)d_in[14];
    const float* edgew = (const float*)d_in[15];
    const float* posw  = (const float*)d_in[16];
    const float* posb  = (const float*)d_in[17];
    const float* fusw  = (const float*)d_in[18];
    const float* fusb  = (const float*)d_in[19];
    float* out = (float*)d_out;
    (void)n_in; (void)in_sizes;

    const int FINAL_N = BB*MM*EE;
    int goff = (out_size >= FINAL_N + BB*NPIX)   ? FINAL_N : -1;
    int soff = (out_size >= FINAL_N + 2*BB*NPIX) ? FINAL_N + BB*NPIX : -1;

    cudaFuncSetAttribute(k_conv2_wmma, cudaFuncAttributeMaxDynamicSharedMemorySize, SMEM_W);

    k_zero<<<1024, 256>>>();
    k_prep_fconst<<<1, EE>>>(c2b, bn2g, bn2b, bn2m, bn2v);
    k_prep_wb<<<(9*EE*C1 + 255)/256, 256>>>(c2w, bn2g, bn2v);
    k_conv1<<<(BB*NPIX*4)/256, 256>>>(img, c1w, c1b, bn1g, bn1b, bn1m, bn1v);
    k_edge<<<BB*NPIX/256, 256>>>(img, seg, edgew, out, goff, soff);
    k_scan<<<1, 512>>>();
    k_scatter<<<BB*NPIX/256, 256>>>(seg);
    k_conv2_wmma<<<dim3(NPIX/128, EE/128, BB), 256, SMEM_W>>>();
    k_pool<<<KK, 256>>>();
    k_fuse<<<dim3(EE/64, (KK + 63)/64), 256>>>(fusw, fusb, posw, posb, cent, out);
}

// round 17
// speedup vs baseline: 1.9942x; 1.9094x over previous
#include <cuda_runtime.h>
#include <cuda_fp16.h>
#include <mma.h>
#include <cstdint>

using namespace nvcuda;

#define HWD   224
#define NPIX  (HWD*HWD)        // 50176
#define BB    2
#define C1    64
#define EE    768
#define MM    196
#define KK    (BB*MM)          // 392
#define PADW  228
#define BNEPS 1e-5f

// ---- static device scratch (no allocation allowed) ----
__device__ __half g_xh[(size_t)BB*PADW*PADW*C1];   // conv1 out (fp16, padded NHWC)
__device__ __half g_wh[9*EE*C1];                   // conv2 w fp16: [t][cout][cin], BN-folded
__device__ float g_feats[77070336];                // conv2 out NHWC [B][HW][E]
__device__ float g_fconst[EE];
__device__ int   g_cnt[KK];
__device__ float g_sim[KK];
__device__ float g_wk[KK];
__device__ int   g_off[KK+1];
__device__ int   g_cur[KK];
__device__ int   g_plist[BB*NPIX];
__device__ float g_concat[KK*2*EE];

// ------------------------------------------------------------------
__global__ void k_zero() {
    float4* ph = (float4*)g_xh;    // 8 halfs per float4
    const int n4 = ((size_t)BB*PADW*PADW*C1)/8;
    for (int i = blockIdx.x*blockDim.x + threadIdx.x; i < n4; i += gridDim.x*blockDim.x)
        ph[i] = make_float4(0.f,0.f,0.f,0.f);
    if (blockIdx.x == 0) {
        for (int i = threadIdx.x; i < KK; i += blockDim.x) {
            g_cnt[i] = 0; g_sim[i] = 0.f; g_cur[i] = 0;
        }
    }
}

// ------------------------------------------------------------------
__global__ void k_prep_fconst(const float* cb, const float* bg, const float* bb_,
                              const float* bm, const float* bv) {
    int c = threadIdx.x;
    if (c < EE) {
        float inv = bg[c] * rsqrtf(bv[c] + BNEPS);
        g_fconst[c] = cb[c]*inv + bb_[c] - bm[c]*inv;
    }
}

// conv2 weights -> [t][cout][cin] fp16, BN-folded
__global__ void k_prep_wb(const float* w, const float* bg, const float* bv) {
    int i = blockIdx.x*blockDim.x + threadIdx.x;
    const int n = 9*EE*C1;
    if (i < n) {
        int cin  = i & 63;
        int r    = i >> 6;
        int cout = r % EE;
        int t    = r / EE;
        float inv = __ldg(&bg[cout]) * rsqrtf(__ldg(&bv[cout]) + BNEPS);
        g_wh[i] = __float2half_rn(__ldg(&w[cout*(C1*9) + cin*9 + t]) * inv);
    }
}

// ------------------------------------------------------------------
// conv1 3->64, 3x3 pad1 + BN + ReLU, fp16 out. 4 threads/pixel x 16 couts.
__global__ void k_conv1(const float* img, const float* w, const float* bias,
                        const float* bg, const float* bb_, const float* bm, const float* bv) {
    int gid = blockIdx.x*blockDim.x + threadIdx.x;   // B*NPIX*4 threads
    int cg  = gid & 3;
    int pix = gid >> 2;
    if (pix >= BB*NPIX) return;
    int b = pix / NPIX, p = pix % NPIX;
    int y = p / HWD, x = p % HWD;

    float in[27];
    #pragma unroll
    for (int ci = 0; ci < 3; ci++)
        #pragma unroll
        for (int ky = 0; ky < 3; ky++)
            #pragma unroll
            for (int kx = 0; kx < 3; kx++) {
                int yy = y + ky - 1, xx = x + kx - 1;
                float v = 0.f;
                if (yy >= 0 && yy < HWD && xx >= 0 && xx < HWD)
                    v = __ldg(&img[((b*3 + ci)*HWD + yy)*HWD + xx]);
                in[ci*9 + ky*3 + kx] = v;
            }
    int c0 = cg*16;
    __half hh[16];
    #pragma unroll
    for (int j = 0; j < 16; j++) {
        int c = c0 + j;
        float acc = 0.f;
        #pragma unroll
        for (int q = 0; q < 27; q++) acc += in[q] * __ldg(&w[c*27 + q]);
        float inv = __ldg(&bg[c]) * rsqrtf(__ldg(&bv[c]) + BNEPS);
        float v = (acc + __ldg(&bias[c]))*inv + __ldg(&bb_[c]) - __ldg(&bm[c])*inv;
        hh[j] = __float2half_rn(fmaxf(v, 0.f));
    }
    size_t base = (((size_t)b*PADW + y + 2)*PADW + x + 2)*C1 + c0;
    *(uint4*)&g_xh[base]     = *(uint4*)hh;
    *(uint4*)&g_xh[base + 8] = *(uint4*)&hh[8];
}

// ------------------------------------------------------------------
__global__ void k_edge(const float* img, const int* seg, const float* ew,
                       float* out, int goff, int soff) {
    __shared__ int   scnt[MM];
    __shared__ float ssim[MM];
    int tid = threadIdx.x;
    if (tid < MM) { scnt[tid] = 0; ssim[tid] = 0.f; }
    __syncthreads();

    int gid = blockIdx.x*256 + tid;
    int b = gid / NPIX, p = gid % NPIX;
    int y = p / HWD, x = p % HWD;

    float e0 = 0.f, e1 = 0.f;
    #pragma unroll
    for (int ky = 0; ky < 3; ky++)
        #pragma unroll
        for (int kx = 0; kx < 3; kx++) {
            int yy = y + ky - 1, xx = x + kx - 1;
            float gr = 0.f;
            if (yy >= 0 && yy < HWD && xx >= 0 && xx < HWD) {
                int base = (b*3*HWD + yy)*HWD + xx;
                gr = (__ldg(&img[base]) + __ldg(&img[base + NPIX]) + __ldg(&img[base + 2*NPIX])) * (1.f/3.f);
            }
            e0 += gr * __ldg(&ew[ky*3 + kx]);
            e1 += gr * __ldg(&ew[9 + ky*3 + kx]);
        }
    float grad = sqrtf(e0*e0 + e1*e1 + 1e-8f);
    float sim  = fminf(fmaxf(1.f - grad, 0.f), 1.f);
    int s = seg[gid];
    if (goff >= 0) out[goff + gid] = grad;
    if (soff >= 0) out[soff + gid] = (float)s;
    atomicAdd(&scnt[s], 1);
    atomicAdd(&ssim[s], sim);
    __syncthreads();
    if (tid < MM) {
        if (scnt[tid]) atomicAdd(&g_cnt[b*MM + tid], scnt[tid]);
        if (ssim[tid] != 0.f) atomicAdd(&g_sim[b*MM + tid], ssim[tid]);
    }
}

// ------------------------------------------------------------------
__global__ void k_scan() {
    __shared__ int s[512];
    int tid = threadIdx.x;
    int v = (tid < KK) ? g_cnt[tid] : 0;
    s[tid] = v;
    __syncthreads();
    for (int d = 1; d < 512; d <<= 1) {
        int t = (tid >= d) ? s[tid - d] : 0;
        __syncthreads();
        s[tid] += t;
        __syncthreads();
    }
    if (tid < KK) {
        g_off[tid] = s[tid] - v;
        g_wk[tid]  = g_sim[tid] / fmaxf((float)v, 1.f);
    }
    if (tid == 0) g_off[KK] = s[511];
}

__global__ void k_scatter(const int* seg) {
    int gid = blockIdx.x*256 + threadIdx.x;
    int b = gid / NPIX, p = gid % NPIX;
    int k = b*MM + seg[gid];
    int pos = atomicAdd(&g_cur[k], 1);
    g_plist[g_off[k] + pos] = p;
}

// ------------------------------------------------------------------
// conv2 via WMMA fp16 single-term + cp.async double-buffered staging.
// block = 128 px x 128 cout, 8 warps, warp = 32 px x 64 cout.
#define LDA 72
#define STAGE_H (2*128*LDA)          // halfs per stage buffer (A + B)
#define OFF_B  (128*LDA)
#define SMEM_W (2*STAGE_H*2)         // 73728 bytes

__device__ __forceinline__ void cp16(uint32_t dst, const void* src) {
    asm volatile("cp.async.cg.shared.global [%0], [%1], 16;" :: "r"(dst), "l"(src) : "memory");
}

__global__ void __launch_bounds__(256) k_conv2_wmma() {
    extern __shared__ __half sm[];
    uint32_t smb = (uint32_t)__cvta_generic_to_shared(sm);
    int tid = threadIdx.x, wid = tid >> 5;
    int p0 = blockIdx.x * 128;
    int c0 = blockIdx.y * 128;
    int b  = blockIdx.z;

    int wm = wid & 3;            // m group: pixels wm*32 .. +31 (2 tiles)
    int wn = wid >> 2;           // n group: couts wn*64 .. +63 (4 tiles)

    wmma::fragment<wmma::accumulator, 16, 16, 16, float> acc[2][4];
    #pragma unroll
    for (int i = 0; i < 2; i++)
        #pragma unroll
        for (int j = 0; j < 4; j++) wmma::fill_fragment(acc[i][j], 0.f);

    // ---- async stage of tap t into buffer buf ----
    auto stage = [&](int t, int buf) {
        int ky = t / 3, kx = t - ky*3;
        uint32_t base = smb + (uint32_t)buf*STAGE_H*2;
        // A: 128 px x 64 cin (1024 x 16B)
        #pragma unroll
        for (int q = 0; q < 4; q++) {
            int u = q*256 + tid;
            int px = u >> 3, c8 = u & 7;
            int p = p0 + px;
            int y = p / HWD, x = p - y*HWD;
            const __half* src = g_xh + (((size_t)b*PADW + y + 2*ky)*PADW + (x + 2*kx))*C1 + c8*8;
            cp16(base + (uint32_t)(px*LDA + c8*8)*2, src);
        }
        // B: 128 cout x 64 cin (1024 x 16B)
        #pragma unroll
        for (int q = 0; q < 4; q++) {
            int u = q*256 + tid;
            int co = u >> 3, c8 = u & 7;
            const __half* src = g_wh + ((size_t)t*EE + c0 + co)*C1 + c8*8;
            cp16(base + (uint32_t)(OFF_B + co*LDA + c8*8)*2, src);
        }
        asm volatile("cp.async.commit_group;" ::: "memory");
    };

    stage(0, 0);

    #pragma unroll 1
    for (int t = 0; t < 9; t++) {
        asm volatile("cp.async.wait_group 0;" ::: "memory");
        __syncthreads();                       // tiles of tap t visible; prior compute done
        if (t < 8) stage(t + 1, (t + 1) & 1);  // overlap with compute below

        const __half* buf = sm + (t & 1)*STAGE_H;
        #pragma unroll
        for (int kc = 0; kc < 4; kc++) {
            wmma::fragment<wmma::matrix_a, 16, 16, 16, __half, wmma::row_major> ah[2];
            #pragma unroll
            for (int i = 0; i < 2; i++)
                wmma::load_matrix_sync(ah[i], &buf[(wm*32 + i*16)*LDA + kc*16], LDA);
            #pragma unroll
            for (int j = 0; j < 4; j++) {
                int nrow = wn*64 + j*16;
                wmma::fragment<wmma::matrix_b, 16, 16, 16, __half, wmma::col_major> bh;
                wmma::load_matrix_sync(bh, &buf[OFF_B + nrow*LDA + kc*16], LDA);
                #pragma unroll
                for (int i = 0; i < 2; i++)
                    wmma::mma_sync(acc[i][j], ah[i], bh, acc[i][j]);
            }
        }
    }

    // ---- epilogue: frags -> smem (fp32, reuse tile mem) -> bias+ReLU -> gmem ----
    __syncthreads();
    float* cs = (float*)sm;      // 128 x 128 floats = 64KB <= 72KB
    #pragma unroll
    for (int i = 0; i < 2; i++)
        #pragma unroll
        for (int j = 0; j < 4; j++)
            wmma::store_matrix_sync(cs + (wm*32 + i*16)*128 + wn*64 + j*16, acc[i][j],
                                    128, wmma::mem_row_major);
    __syncthreads();

    #pragma unroll
    for (int q = 0; q < 16; q++) {
        int u = q*256 + tid;             // float4 index, 0..4095
        int row = u >> 5, col4 = u & 31;
        float4 v = ((const float4*)cs)[u];
        int cb = c0 + col4*4;
        v.x = fmaxf(v.x + __ldg(&g_fconst[cb+0]), 0.f);
        v.y = fmaxf(v.y + __ldg(&g_fconst[cb+1]), 0.f);
        v.z = fmaxf(v.z + __ldg(&g_fconst[cb+2]), 0.f);
        v.w = fmaxf(v.w + __ldg(&g_fconst[cb+3]), 0.f);
        *(float4*)&g_feats[((size_t)b*NPIX + p0 + row)*EE + cb] = v;
    }
}

// ------------------------------------------------------------------
// per-(b,seg) mean/max pooling over pixel list; each thread owns 3 channels
__global__ void k_pool() {
    __shared__ int sp[256];
    int k = blockIdx.x;
    int b = k / MM;
    int tid = threadIdx.x;
    int cnt = g_cnt[k];
    int off = g_off[k];
    const float* fb = g_feats + (size_t)b*NPIX*EE;

    float s0=0.f, s1=0.f, s2=0.f, m0=0.f, m1=0.f, m2=0.f;
    for (int base = 0; base < cnt; base += 256) {
        int nchunk = min(256, cnt - base);
        __syncthreads();
        if (tid < nchunk) sp[tid] = g_plist[off + base + tid];
        __syncthreads();
        int i = 0;
        for (; i + 1 < nchunk; i += 2) {
            const float* f0 = fb + (size_t)sp[i]*EE + tid;
            const float* f1 = fb + (size_t)sp[i+1]*EE + tid;
            float a0 = f0[0], b0 = f0[256], c0v = f0[512];
            float a1 = f1[0], b1 = f1[256], c1v = f1[512];
            s0 += a0 + a1; s1 += b0 + b1; s2 += c0v + c1v;
            m0 = fmaxf(m0, fmaxf(a0, a1));
            m1 = fmaxf(m1, fmaxf(b0, b1));
            m2 = fmaxf(m2, fmaxf(c0v, c1v));
        }
        if (i < nchunk) {
            const float* f0 = fb + (size_t)sp[i]*EE + tid;
            float a0 = f0[0], b0 = f0[256], c0v = f0[512];
            s0 += a0; s1 += b0; s2 += c0v;
            m0 = fmaxf(m0, a0); m1 = fmaxf(m1, b0); m2 = fmaxf(m2, c0v);
        }
    }
    float n = fmaxf((float)cnt, 1.f);
    float* dst = g_concat + (size_t)k*1536;
    dst[tid]        = s0/n;  dst[256 + tid]  = s1/n;  dst[512 + tid]  = s2/n;
    dst[768 + tid]  = m0;    dst[1024 + tid] = m1;    dst[1280 + tid] = m2;
}

// ------------------------------------------------------------------
// fused = concat @ fusion_w^T + b, *W_k, + positional embedding
__global__ void k_fuse(const float* fw, const float* fbias, const float* pw,
                       const float* pb, const float* cent, float* out) {
    __shared__ float As[16][68];
    __shared__ float Bs[16][68];
    int tid = threadIdx.x;
    int d0 = blockIdx.x * 64;
    int r0 = blockIdx.y * 64;
    int tx = tid % 16, ty2 = tid / 16;

    float acc[4][4];
    #pragma unroll
    for (int i = 0; i < 4; i++)
        #pragma unroll
        for (int j = 0; j < 4; j++) acc[i][j] = 0.f;

    for (int kk = 0; kk < 2*EE; kk += 16) {
        {
            int ar = tid >> 2, ac4 = tid & 3;
            int r = r0 + ar;
            float4 v = make_float4(0.f,0.f,0.f,0.f);
            if (r < KK)
                v = ((const float4*)(g_concat + (size_t)r*1536 + kk))[ac4];
            As[ac4*4+0][ar] = v.x; As[ac4*4+1][ar] = v.y;
            As[ac4*4+2][ar] = v.z; As[ac4*4+3][ar] = v.w;
        }
        {
            int dd = tid >> 2, cc4 = tid & 3;
            float4 v = ((const float4*)(fw + (size_t)(d0 + dd)*1536 + kk))[cc4];
            Bs[cc4*4+0][dd] = v.x; Bs[cc4*4+1][dd] = v.y;
            Bs[cc4*4+2][dd] = v.z; Bs[cc4*4+3][dd] = v.w;
        }
        __syncthreads();
        #pragma unroll
        for (int q = 0; q < 16; q++) {
            float4 a = *(const float4*)&As[q][ty2*4];
            float4 bv = *(const float4*)&Bs[q][tx*4];
            const float* ap = (const float*)&a;
            const float* bp = (const float*)&bv;
            #pragma unroll
            for (int i = 0; i < 4; i++)
                #pragma unroll
                for (int j = 0; j < 4; j++)
                    acc[i][j] += ap[i] * bp[j];
        }
        __syncthreads();
    }

    #pragma unroll
    for (int i = 0; i < 4; i++) {
        int r = r0 + ty2*4 + i;
        if (r >= KK) continue;
        float wk = g_wk[r];
        float cx = __ldg(&cent[r*2 + 0]) * (1.f/224.f);
        float cy = __ldg(&cent[r*2 + 1]) * (1.f/224.f);
        #pragma unroll
        for (int j = 0; j < 4; j++) {
            int d = d0 + tx*4 + j;
            float v = (acc[i][j] + __ldg(&fbias[d])) * wk;
            v += cx*__ldg(&pw[d*2 + 0]) + cy*__ldg(&pw[d*2 + 1]) + __ldg(&pb[d]);
            out[(size_t)r*EE + d] = v;
        }
    }
}

// ------------------------------------------------------------------
extern "C" void kernel_launch(void* const* d_in, const int* in_sizes, int n_in,
                              void* d_out, int out_size) {
    const float* img   = (const float*)d_in[0];
    const int*   seg   = (const int*)d_in[1];
    const float* cent  = (const float*)d_in[2];
    const float* c1w   = (const float*)d_in[3];
    const float* c1b   = (const float*)d_in[4];
    const float* bn1g  = (const float*)d_in[5];
    const float* bn1b  = (const float*)d_in[6];
    const float* bn1m  = (const float*)d_in[7];
    const float* bn1v  = (const float*)d_in[8];
    const float* c2w   = (const float*)d_in[9];
    const float* c2b   = (const float*)d_in[10];
    const float* bn2g  = (const float*)d_in[11];
    const float* bn2b  = (const float*)d_in[12];
    const float* bn2m  = (const float*)d_in[13];
    const float* bn2v  = (const float*)d_in[14];
    const float* edgew = (const float*)d_in[15];
    const float* posw  = (const float*)d_in[16];
    const float* posb  = (const float*)d_in[17];
    const float* fusw  = (const float*)d_in[18];
    const float* fusb  = (const float*)d_in[19];
    float* out = (float*)d_out;
    (void)n_in; (void)in_sizes;

    const int FINAL_N = BB*MM*EE;
    int goff = (out_size >= FINAL_N + BB*NPIX)   ? FINAL_N : -1;
    int soff = (out_size >= FINAL_N + 2*BB*NPIX) ? FINAL_N + BB*NPIX : -1;

    cudaFuncSetAttribute(k_conv2_wmma, cudaFuncAttributeMaxDynamicSharedMemorySize, SMEM_W);

    k_zero<<<1024, 256>>>();
    k_prep_fconst<<<1, EE>>>(c2b, bn2g, bn2b, bn2m, bn2v);
    k_prep_wb<<<(9*EE*C1 + 255)/256, 256>>>(c2w, bn2g, bn2v);
    k_conv1<<<(BB*NPIX*4)/256, 256>>>(img, c1w, c1b, bn1g, bn1b, bn1m, bn1v);
    k_edge<<<BB*NPIX/256, 256>>>(img, seg, edgew, out, goff, soff);
    k_scan<<<1, 512>>>();
    k_scatter<<<BB*NPIX/256, 256>>>(seg);
    k_conv2_wmma<<<dim3(NPIX/128, EE/128, BB), 256, SMEM_W>>>();
    k_pool<<<KK, 256>>>();
    k_fuse<<<dim3(EE/64, (KK + 63)/64), 256>>>(fusw, fusb, posw, posb, cent, out);
}